// round 11
// baseline (speedup 1.0000x reference)
#include <cuda_runtime.h>
#include <math.h>

// Problem constants
#define NB 2
#define NP 512
#define BN (NB*NP)
#define MAXN 512
#define THETA0 0.78539816339744831f   // 2*pi/8
#define INV2PI 0.15915494309189535f

// ---------------- scratch (static __device__, no allocation) ----------------
static __device__ float d_p1[BN*2];
static __device__ float d_F0[BN*32];            // raw fluid feats (16 ch x 2 comp)
static __device__ float d_Y [1024*6272];        // per-j transformed features (reused per layer)
static __device__ float d_KK0[32*1568];
static __device__ float d_KK1[64*3136];
static __device__ float d_KK2[64*6272];
static __device__ float d_KK3[128*3136];
static __device__ float d_KK4[64*304];
static __device__ float d_R0[BN*64], d_A0[BN*64];
static __device__ float d_R1[BN*64], d_A1[BN*64];
static __device__ float d_R2[BN*128], d_A2[BN*128];
static __device__ float d_R3[BN*64], d_A3[BN*64];
static __device__ unsigned short d_nbrJ[BN*MAXN];
static __device__ unsigned int   d_nbrG[BN*MAXN];
static __device__ float4         d_nbrW[BN*MAXN];
static __device__ int            d_nbrCnt[BN];

// ---------------- prep: p1/v1, raw feature assembly ----------------
__global__ void prep_kernel(const float* __restrict__ p0_enc,
                            const float* __restrict__ v0_enc,
                            const float* __restrict__ p0,
                            const float* __restrict__ v0,
                            const float* __restrict__ a)
{
    int idx = blockIdx.x*blockDim.x + threadIdx.x;
    if (idx >= BN*16) return;
    int bn = idx >> 4;
    int c  = idx & 15;
    float fx, fy;
    if (c == 0) {                      // v1 = v0 + a
        fx = v0[bn*2]   + a[bn*2];
        fy = v0[bn*2+1] + a[bn*2+1];
    } else if (c == 1) {               // p1 = p0 + v0 + 0.5*a
        fx = p0[bn*2]   + v0[bn*2]   + 0.5f*a[bn*2];
        fy = p0[bn*2+1] + v0[bn*2+1] + 0.5f*a[bn*2+1];
        d_p1[bn*2] = fx; d_p1[bn*2+1] = fy;
    } else if (c < 9) {                // v0_enc channels
        int t = c - 2;
        fx = v0_enc[(bn*7+t)*2]; fy = v0_enc[(bn*7+t)*2+1];
    } else {                           // p0_enc channels
        int t = c - 9;
        fx = p0_enc[(bn*7+t)*2]; fy = p0_enc[(bn*7+t)*2+1];
    }
    d_F0[bn*32 + c*2]     = fx;
    d_F0[bn*32 + c*2 + 1] = fy;
}

// ---------------- pair geometry -> compacted deterministic neighbor lists ----
__global__ void __launch_bounds__(256) pair_kernel(const float* __restrict__ mask)
{
    int bn  = blockIdx.x;
    int b   = bn >> 9;
    int i   = bn & 511;
    int tid = threadIdx.x;
    __shared__ float sred[256];
    __shared__ int   sscan[256];

    float pix = d_p1[bn*2], piy = d_p1[bn*2+1];
    int base = b * NP;

    float relx[2], rely[2], dd[2], wm[2];
    float sum = 0.f;
    #pragma unroll
    for (int k = 0; k < 2; k++) {
        int j = 2*tid + k;
        float rx = d_p1[(base+j)*2]   - pix;
        float ry = d_p1[(base+j)*2+1] - piy;
        float d  = sqrtf(rx*rx + ry*ry + 1e-12f) * 0.025f;   // /RADIUS
        float w  = fmaxf(1.f - d*d, 0.f);
        w = w*w*w;
        float wmv = w * mask[base+j];
        relx[k]=rx; rely[k]=ry; dd[k]=d; wm[k]=wmv;
        sum += wmv;
    }
    sred[tid] = sum;
    __syncthreads();
    for (int s = 128; s > 0; s >>= 1) {
        if (tid < s) sred[tid] += sred[tid+s];
        __syncthreads();
    }
    float denom = sred[0] + 1e-6f;

    int v0 = wm[0] > 0.f;
    int v1 = wm[1] > 0.f;
    int cntt = v0 + v1;
    sscan[tid] = cntt;
    __syncthreads();
    for (int off = 1; off < 256; off <<= 1) {
        int val = (tid >= off) ? sscan[tid-off] : 0;
        __syncthreads();
        sscan[tid] += val;
        __syncthreads();
    }
    int pos = sscan[tid] - cntt;   // exclusive prefix, preserves j order

    #pragma unroll
    for (int k = 0; k < 2; k++) {
        if (wm[k] > 0.f) {
            int j = 2*tid + k;
            float wb = wm[k] / denom;
            float d  = dd[k];
            float rc = fminf(fmaxf(d*3.f - 0.5f, 0.f), 2.f);
            float r0f = floorf(rc);
            float wr  = rc - r0f;
            int r0i = (int)r0f;
            int r1i = min(r0i + 1, 2);
            float rxx = (j == i) ? 1.f : relx[k];
            float ryy = (j == i) ? 0.f : rely[k];
            float ang = atan2f(ryy, rxx) * INV2PI;
            ang -= floorf(ang);            // frac -> [0,1)
            float tc  = ang * 16.f;
            float t0f = floorf(tc);
            float wt  = tc - t0f;
            int t0i = ((int)t0f) & 15;
            int t1i = (t0i + 1) & 15;
            unsigned g00 = (unsigned)(r0i*16 + t0i);
            unsigned g01 = (unsigned)(r0i*16 + t1i);
            unsigned g10 = (unsigned)(r1i*16 + t0i);
            unsigned g11 = (unsigned)(r1i*16 + t1i);
            int off2 = bn*MAXN + pos;
            d_nbrJ[off2] = (unsigned short)j;
            d_nbrG[off2] = g00 | (g01<<8) | (g10<<16) | (g11<<24);
            d_nbrW[off2] = make_float4((1.f-wr)*(1.f-wt)*wb,
                                       (1.f-wr)*wt*wb,
                                       wr*(1.f-wt)*wb,
                                       wr*wt*wb);
            pos++;
        }
    }
    if (tid == 0) d_nbrCnt[bn] = sscan[255];
}

// ---------------- weight expansion kernels ----------------
// Generic layer (1..3): KK[(c*8+n), g*OM + o*8+m]
//   g<48 : Wc[o,c,(n-m)&7, r, (t-2m)&15]
//   g=48 : Wd[o,c,(m-n)&7]
template<int C, int O>
__global__ void expand_kernel(const float* __restrict__ Wc,
                              const float* __restrict__ Wd,
                              float* __restrict__ KK)
{
    constexpr int OM = O*8, NCOL = 49*OM, CN = C*8;
    int idx = blockIdx.x*blockDim.x + threadIdx.x;
    if (idx >= CN*NCOL) return;
    int k   = idx / NCOL;
    int col = idx - k*NCOL;
    int g   = col / OM;
    int om  = col - g*OM;
    int c = k>>3, n = k&7, o = om>>3, m = om&7;
    float v;
    if (g < 48) {
        int r = g>>4, t = g&15;
        v = Wc[(((o*C + c)*8 + ((n-m)&7))*3 + r)*16 + ((t - 2*m)&15)];
    } else {
        v = Wd[(o*C + c)*8 + ((m-n)&7)];
    }
    KK[k*NCOL + col] = v;
}

// Layer 0: lifts folded in. Input is raw feats (16 ch x 2 comp, K=32).
// KK0[(c*2+a), g*32 + o*8+m] = sum_n basis_a[n] * W...
__global__ void expand0_kernel(const float* __restrict__ Wc,
                               const float* __restrict__ Wd,
                               const float* __restrict__ lc,
                               const float* __restrict__ ld,
                               float* __restrict__ KK)
{
    int idx = blockIdx.x*blockDim.x + threadIdx.x;
    if (idx >= 32*1568) return;
    int k   = idx / 1568;
    int col = idx - k*1568;
    int c = k>>1, a = k&1;
    int g = col >> 5;
    int om = col & 31;
    int o = om>>3, m = om&7;
    float s = 0.f;
    if (g < 48) {
        int r = g>>4, t = g&15;
        float l0 = lc[0], l1 = lc[1];
        #pragma unroll
        for (int n = 0; n < 8; n++) {
            float sn, cs; sincosf((float)n*THETA0, &sn, &cs);
            float bas = a ? (l0*sn + l1*cs) : (l0*cs - l1*sn);
            s += bas * Wc[(((o*16 + c)*8 + ((n-m)&7))*3 + r)*16 + ((t - 2*m)&15)];
        }
    } else {
        float l0 = ld[0], l1 = ld[1];
        #pragma unroll
        for (int n = 0; n < 8; n++) {
            float sn, cs; sincosf((float)n*THETA0, &sn, &cs);
            float bas = a ? (l0*sn + l1*cs) : (l0*cs - l1*sn);
            s += bas * Wd[(o*16 + c)*8 + ((m-n)&7)];
        }
    }
    KK[k*1568 + col] = s;
}

// Layer 4: rho1 projection folded in. Output cols = g*6 + o*2 + a (294, stride 304).
__global__ void expand4_kernel(const float* __restrict__ Wc,
                               const float* __restrict__ Wd,
                               const float* __restrict__ pc,
                               const float* __restrict__ pd,
                               float* __restrict__ KK)
{
    int idx = blockIdx.x*blockDim.x + threadIdx.x;
    if (idx >= 64*294) return;
    int k   = idx / 294;
    int col = idx - k*294;
    int c = k>>3, n = k&7;
    int g  = col / 6;
    int oa = col - g*6;
    int o = oa>>1, a = oa&1;
    float s = 0.f;
    if (g < 48) {
        int r = g>>4, t = g&15;
        float c0 = pc[0], c1 = pc[1];
        #pragma unroll
        for (int m = 0; m < 8; m++) {
            float sn, cs; sincosf((float)m*THETA0, &sn, &cs);
            float bas = a ? (c0*sn + c1*cs) : (c0*cs - c1*sn);
            s += bas * Wc[(((o*8 + c)*8 + ((n-m)&7))*3 + r)*16 + ((t - 2*m)&15)];
        }
    } else {
        float d0 = pd[0], d1 = pd[1];
        #pragma unroll
        for (int m = 0; m < 8; m++) {
            float sn, cs; sincosf((float)m*THETA0, &sn, &cs);
            float bas = a ? (d0*sn + d1*cs) : (d0*cs - d1*sn);
            s += bas * Wd[(o*8 + c)*8 + ((m-n)&7)];
        }
    }
    KK[k*304 + col] = s;
}

// ---------------- GEMM: Y[1024 x NCOLP] = A[1024 x K] * KK[K x NCOLP] ----------
template<int K>
__global__ void __launch_bounds__(256)
gemm_kernel(const float* __restrict__ A, const float* __restrict__ B,
            float* __restrict__ C, int ncolp)
{
    __shared__ float As[16][64];   // [k][m]
    __shared__ float Bs[16][64];   // [k][n]
    int tid  = threadIdx.x;
    int row0 = blockIdx.y * 64;
    int col0 = blockIdx.x * 64;
    int ty = tid >> 4, tx = tid & 15;
    float acc[4][4] = {};

    for (int k0 = 0; k0 < K; k0 += 16) {
        {   // A tile: 64 rows x 16 k
            int r  = tid >> 2;
            int kq = (tid & 3) * 4;
            float4 av = *(const float4*)(A + (size_t)(row0 + r)*K + k0 + kq);
            As[kq+0][r] = av.x; As[kq+1][r] = av.y;
            As[kq+2][r] = av.z; As[kq+3][r] = av.w;
        }
        {   // B tile: 16 k x 64 n
            int kr = tid >> 4;
            int nq = (tid & 15) * 4;
            int col = col0 + nq;
            float4 bv = make_float4(0.f,0.f,0.f,0.f);
            if (col < ncolp)
                bv = *(const float4*)(B + (size_t)(k0 + kr)*ncolp + col);
            *(float4*)&Bs[kr][nq] = bv;
        }
        __syncthreads();
        #pragma unroll
        for (int kk = 0; kk < 16; kk++) {
            float4 av = *(const float4*)&As[kk][ty*4];
            float4 bv = *(const float4*)&Bs[kk][tx*4];
            float aa[4] = {av.x, av.y, av.z, av.w};
            float bb[4] = {bv.x, bv.y, bv.z, bv.w};
            #pragma unroll
            for (int ii = 0; ii < 4; ii++)
                #pragma unroll
                for (int jj = 0; jj < 4; jj++)
                    acc[ii][jj] += aa[ii] * bb[jj];
        }
        __syncthreads();
    }
    int colw = col0 + tx*4;
    if (colw < ncolp) {
        #pragma unroll
        for (int ii = 0; ii < 4; ii++) {
            float4 v = make_float4(acc[ii][0], acc[ii][1], acc[ii][2], acc[ii][3]);
            *(float4*)(C + (size_t)(row0 + ty*4 + ii)*ncolp + colw) = v;
        }
    }
}

// ---------------- neighbor gather ----------------
// MODE 0: out = conv + dense; MODE 1: concat(conv, dense) (layer 0);
// MODE 2: out = conv + dense + residual
template<int OM, int NI, int MODE>
__global__ void __launch_bounds__(OM*NI)
gather_kernel(const float* __restrict__ Y, int ncolp,
              const float* __restrict__ Res, float* __restrict__ Out)
{
    int tid  = threadIdx.x;
    int ig   = tid / OM;
    int lane = tid % OM;
    int bn   = blockIdx.x*NI + ig;
    int b    = bn >> 9;
    const float* Yb = Y + (size_t)(b*NP)*ncolp;
    int cnt = d_nbrCnt[bn];
    int pb  = bn*MAXN;
    float a0=0.f, a1=0.f, a2=0.f, a3=0.f;
    for (int e = 0; e < cnt; e++) {
        unsigned j  = d_nbrJ[pb+e];
        unsigned gp = d_nbrG[pb+e];
        float4   w  = d_nbrW[pb+e];
        const float* Yj = Yb + (size_t)j*ncolp + lane;
        a0 += w.x * __ldg(Yj + ( gp        & 255u)*OM);
        a1 += w.y * __ldg(Yj + ((gp >>  8) & 255u)*OM);
        a2 += w.z * __ldg(Yj + ((gp >> 16) & 255u)*OM);
        a3 += w.w * __ldg(Yj + ( gp >> 24        )*OM);
    }
    float conv  = (a0 + a1) + (a2 + a3);
    float dense = __ldg(Yb + (size_t)(bn & 511)*ncolp + 48*OM + lane);
    if (MODE == 1) {
        Out[bn*(2*OM) + lane]      = conv;
        Out[bn*(2*OM) + OM + lane] = dense;
    } else {
        float v = conv + dense;
        if (MODE == 2) v += Res[bn*OM + lane];
        Out[bn*OM + lane] = v;
    }
}

// Final layer gather: OM=6 (projected), epilogue writes p_corr/v_corr/m_matrix
__global__ void __launch_bounds__(128)
gather4_kernel(const float* __restrict__ Y, const float* __restrict__ p0,
               float* __restrict__ out)
{
    int tid  = threadIdx.x;
    int ig   = tid >> 3;
    int lane = tid & 7;
    int bn   = blockIdx.x*16 + ig;
    if (lane >= 6) return;
    int b = bn >> 9;
    const float* Yb = Y + (size_t)(b*NP)*304;
    int cnt = d_nbrCnt[bn];
    int pb  = bn*MAXN;
    float a0=0.f, a1=0.f, a2=0.f, a3=0.f;
    for (int e = 0; e < cnt; e++) {
        unsigned j  = d_nbrJ[pb+e];
        unsigned gp = d_nbrG[pb+e];
        float4   w  = d_nbrW[pb+e];
        const float* Yj = Yb + (size_t)j*304 + lane;
        a0 += w.x * __ldg(Yj + ( gp        & 255u)*6);
        a1 += w.y * __ldg(Yj + ((gp >>  8) & 255u)*6);
        a2 += w.z * __ldg(Yj + ((gp >> 16) & 255u)*6);
        a3 += w.w * __ldg(Yj + ( gp >> 24        )*6);
    }
    float s = (a0 + a1) + (a2 + a3)
            + __ldg(Yb + (size_t)(bn & 511)*304 + 288 + lane);
    float pcv = s * 0.0078125f;    // CORR = 1/128
    int o = lane >> 1, a = lane & 1;
    if (o == 0) {
        float pc = d_p1[bn*2 + a] + pcv;
        out[bn*2 + a]          = pc;                      // p_corr
        out[2*BN + bn*2 + a]   = pc - p0[bn*2 + a];       // v_corr (DT=1)
    } else {
        out[4*BN + (bn*2 + (o-1))*2 + a] = pcv;           // m_matrix
    }
}

// ---------------- mag_act ----------------
template<int C>
__global__ void magact_kernel(const float* __restrict__ Y, float* __restrict__ Xo)
{
    int idx = blockIdx.x*blockDim.x + threadIdx.x;
    if (idx >= BN*C) return;
    const float4* y4 = (const float4*)(Y + idx*8);
    float4 a = y4[0], b = y4[1];
    float mg = 1e-6f + a.x*a.x + a.y*a.y + a.z*a.z + a.w*a.w
                     + b.x*b.x + b.y*b.y + b.z*b.z + b.w*b.w;
    float s = fmaxf(mg - 0.2f, 0.f) / mg;
    float4* o4 = (float4*)(Xo + idx*8);
    o4[0] = make_float4(a.x*s, a.y*s, a.z*s, a.w*s);
    o4[1] = make_float4(b.x*s, b.y*s, b.z*s, b.w*s);
}

// ---------------- launch ----------------
extern "C" void kernel_launch(void* const* d_in, const int* in_sizes, int n_in,
                              void* d_out, int out_size)
{
    (void)in_sizes; (void)n_in; (void)out_size;
    const float* p0_enc = (const float*)d_in[0];
    const float* v0_enc = (const float*)d_in[1];
    const float* p0     = (const float*)d_in[2];
    const float* v0     = (const float*)d_in[3];
    const float* a      = (const float*)d_in[4];
    const float* fm     = (const float*)d_in[5];
    const float* lift_c0= (const float*)d_in[6];
    const float* Wc0    = (const float*)d_in[7];
    const float* lift_d0= (const float*)d_in[8];
    const float* Wd0    = (const float*)d_in[9];
    const float* Wc1    = (const float*)d_in[10];
    const float* Wd1    = (const float*)d_in[11];
    const float* Wc2    = (const float*)d_in[12];
    const float* Wd2    = (const float*)d_in[13];
    const float* Wc3    = (const float*)d_in[14];
    const float* Wd3    = (const float*)d_in[15];
    const float* Wc4    = (const float*)d_in[16];
    const float* pc4    = (const float*)d_in[17];
    const float* Wd4    = (const float*)d_in[18];
    const float* pd4    = (const float*)d_in[19];
    float* out = (float*)d_out;

    float *pF0, *pY, *pK0, *pK1, *pK2, *pK3, *pK4;
    float *pR0, *pA0, *pR1, *pA1, *pR2, *pA2, *pR3, *pA3;
    cudaGetSymbolAddress((void**)&pF0, d_F0);
    cudaGetSymbolAddress((void**)&pY,  d_Y);
    cudaGetSymbolAddress((void**)&pK0, d_KK0);
    cudaGetSymbolAddress((void**)&pK1, d_KK1);
    cudaGetSymbolAddress((void**)&pK2, d_KK2);
    cudaGetSymbolAddress((void**)&pK3, d_KK3);
    cudaGetSymbolAddress((void**)&pK4, d_KK4);
    cudaGetSymbolAddress((void**)&pR0, d_R0);
    cudaGetSymbolAddress((void**)&pA0, d_A0);
    cudaGetSymbolAddress((void**)&pR1, d_R1);
    cudaGetSymbolAddress((void**)&pA1, d_A1);
    cudaGetSymbolAddress((void**)&pR2, d_R2);
    cudaGetSymbolAddress((void**)&pA2, d_A2);
    cudaGetSymbolAddress((void**)&pR3, d_R3);
    cudaGetSymbolAddress((void**)&pA3, d_A3);

    prep_kernel<<<(BN*16 + 127)/128, 128>>>(p0_enc, v0_enc, p0, v0, a);
    pair_kernel<<<BN, 256>>>(fm);

    // weight expansions (all independent of particle data)
    expand0_kernel<<<(32*1568 + 255)/256, 256>>>(Wc0, Wd0, lift_c0, lift_d0, pK0);
    expand_kernel<8,8>  <<<(64*3136 + 255)/256, 256>>>(Wc1, Wd1, pK1);
    expand_kernel<8,16> <<<(64*6272 + 255)/256, 256>>>(Wc2, Wd2, pK2);
    expand_kernel<16,8> <<<(128*3136 + 255)/256, 256>>>(Wc3, Wd3, pK3);
    expand4_kernel<<<(64*294 + 255)/256, 256>>>(Wc4, Wd4, pc4, pd4, pK4);

    // L0: K=32 raw feats -> Y[.,1568]; gather concat(conv32, dense32) -> R0
    gemm_kernel<32><<<dim3((1568+63)/64, 16), 256>>>(pF0, pK0, pY, 1568);
    gather_kernel<32,4,1><<<BN/4, 128>>>(pY, 1568, nullptr, pR0);
    magact_kernel<8><<<(BN*8 + 127)/128, 128>>>(pR0, pA0);

    // L1: C=8 -> O=8, residual += R0
    gemm_kernel<64><<<dim3((3136+63)/64, 16), 256>>>(pA0, pK1, pY, 3136);
    gather_kernel<64,2,2><<<BN/2, 128>>>(pY, 3136, pR0, pR1);
    magact_kernel<8><<<(BN*8 + 127)/128, 128>>>(pR1, pA1);

    // L2: C=8 -> O=16
    gemm_kernel<64><<<dim3((6272+63)/64, 16), 256>>>(pA1, pK2, pY, 6272);
    gather_kernel<128,1,0><<<BN, 128>>>(pY, 6272, nullptr, pR2);
    magact_kernel<16><<<(BN*16 + 127)/128, 128>>>(pR2, pA2);

    // L3: C=16 -> O=8
    gemm_kernel<128><<<dim3((3136+63)/64, 16), 256>>>(pA2, pK3, pY, 3136);
    gather_kernel<64,2,0><<<BN/2, 128>>>(pY, 3136, nullptr, pR3);
    magact_kernel<8><<<(BN*8 + 127)/128, 128>>>(pR3, pA3);

    // L4: C=8 -> projected 6 outputs, fused epilogue
    gemm_kernel<64><<<dim3((304+63)/64, 16), 256>>>(pA3, pK4, pY, 304);
    gather4_kernel<<<BN/16, 128>>>(pY, p0, out);
}

// round 12
// speedup vs baseline: 1.0133x; 1.0133x over previous
#include <cuda_runtime.h>
#include <math.h>

// Problem constants
#define NB 2
#define NP 512
#define BN (NB*NP)
#define MAXN 512
#define THETA0 0.78539816339744831f   // 2*pi/8
#define INV2PI 0.15915494309189535f

// ---------------- scratch (static __device__, no allocation) ----------------
static __device__ float d_p1[BN*2];
static __device__ float d_F0[BN*32];            // raw fluid feats (16 ch x 2 comp)
static __device__ float d_Y [1024*6272];        // per-j transformed features (reused per layer)
static __device__ float d_KK0[32*1568];
static __device__ float d_KK1[64*3136];
static __device__ float d_KK2[64*6272];
static __device__ float d_KK3[128*3136];
static __device__ float d_KK4[64*304];
static __device__ float d_R0[BN*64], d_A0[BN*64];
static __device__ float d_R1[BN*64], d_A1[BN*64];
static __device__ float d_R2[BN*128], d_A2[BN*128];
static __device__ float d_R3[BN*64], d_A3[BN*64];
static __device__ unsigned short d_nbrJ[BN*MAXN];
static __device__ unsigned int   d_nbrG[BN*MAXN];
static __device__ float4         d_nbrW[BN*MAXN];
static __device__ int            d_nbrCnt[BN];

// ---------------- prep: p1/v1, raw feature assembly ----------------
__global__ void prep_kernel(const float* __restrict__ p0_enc,
                            const float* __restrict__ v0_enc,
                            const float* __restrict__ p0,
                            const float* __restrict__ v0,
                            const float* __restrict__ a)
{
    int idx = blockIdx.x*blockDim.x + threadIdx.x;
    if (idx >= BN*16) return;
    int bn = idx >> 4;
    int c  = idx & 15;
    float fx, fy;
    if (c == 0) {                      // v1 = v0 + a
        fx = v0[bn*2]   + a[bn*2];
        fy = v0[bn*2+1] + a[bn*2+1];
    } else if (c == 1) {               // p1 = p0 + v0 + 0.5*a
        fx = p0[bn*2]   + v0[bn*2]   + 0.5f*a[bn*2];
        fy = p0[bn*2+1] + v0[bn*2+1] + 0.5f*a[bn*2+1];
        d_p1[bn*2] = fx; d_p1[bn*2+1] = fy;
    } else if (c < 9) {                // v0_enc channels
        int t = c - 2;
        fx = v0_enc[(bn*7+t)*2]; fy = v0_enc[(bn*7+t)*2+1];
    } else {                           // p0_enc channels
        int t = c - 9;
        fx = p0_enc[(bn*7+t)*2]; fy = p0_enc[(bn*7+t)*2+1];
    }
    d_F0[bn*32 + c*2]     = fx;
    d_F0[bn*32 + c*2 + 1] = fy;
}

// ---------------- pair geometry -> compacted deterministic neighbor lists ----
__global__ void __launch_bounds__(256) pair_kernel(const float* __restrict__ mask)
{
    int bn  = blockIdx.x;
    int b   = bn >> 9;
    int i   = bn & 511;
    int tid = threadIdx.x;
    __shared__ float sred[256];
    __shared__ int   sscan[256];

    float pix = d_p1[bn*2], piy = d_p1[bn*2+1];
    int base = b * NP;

    float relx[2], rely[2], dd[2], wm[2];
    float sum = 0.f;
    #pragma unroll
    for (int k = 0; k < 2; k++) {
        int j = 2*tid + k;
        float rx = d_p1[(base+j)*2]   - pix;
        float ry = d_p1[(base+j)*2+1] - piy;
        float d  = sqrtf(rx*rx + ry*ry + 1e-12f) * 0.025f;   // /RADIUS
        float w  = fmaxf(1.f - d*d, 0.f);
        w = w*w*w;
        float wmv = w * mask[base+j];
        relx[k]=rx; rely[k]=ry; dd[k]=d; wm[k]=wmv;
        sum += wmv;
    }
    sred[tid] = sum;
    __syncthreads();
    for (int s = 128; s > 0; s >>= 1) {
        if (tid < s) sred[tid] += sred[tid+s];
        __syncthreads();
    }
    float denom = sred[0] + 1e-6f;

    int v0 = wm[0] > 0.f;
    int v1 = wm[1] > 0.f;
    int cntt = v0 + v1;
    sscan[tid] = cntt;
    __syncthreads();
    for (int off = 1; off < 256; off <<= 1) {
        int val = (tid >= off) ? sscan[tid-off] : 0;
        __syncthreads();
        sscan[tid] += val;
        __syncthreads();
    }
    int pos = sscan[tid] - cntt;   // exclusive prefix, preserves j order

    #pragma unroll
    for (int k = 0; k < 2; k++) {
        if (wm[k] > 0.f) {
            int j = 2*tid + k;
            float wb = wm[k] / denom;
            float d  = dd[k];
            float rc = fminf(fmaxf(d*3.f - 0.5f, 0.f), 2.f);
            float r0f = floorf(rc);
            float wr  = rc - r0f;
            int r0i = (int)r0f;
            int r1i = min(r0i + 1, 2);
            float rxx = (j == i) ? 1.f : relx[k];
            float ryy = (j == i) ? 0.f : rely[k];
            float ang = atan2f(ryy, rxx) * INV2PI;
            ang -= floorf(ang);            // frac -> [0,1)
            float tc  = ang * 16.f;
            float t0f = floorf(tc);
            float wt  = tc - t0f;
            int t0i = ((int)t0f) & 15;
            int t1i = (t0i + 1) & 15;
            unsigned g00 = (unsigned)(r0i*16 + t0i);
            unsigned g01 = (unsigned)(r0i*16 + t1i);
            unsigned g10 = (unsigned)(r1i*16 + t0i);
            unsigned g11 = (unsigned)(r1i*16 + t1i);
            int off2 = bn*MAXN + pos;
            d_nbrJ[off2] = (unsigned short)j;
            d_nbrG[off2] = g00 | (g01<<8) | (g10<<16) | (g11<<24);
            d_nbrW[off2] = make_float4((1.f-wr)*(1.f-wt)*wb,
                                       (1.f-wr)*wt*wb,
                                       wr*(1.f-wt)*wb,
                                       wr*wt*wb);
            pos++;
        }
    }
    if (tid == 0) d_nbrCnt[bn] = sscan[255];
}

// ---------------- weight expansion kernels ----------------
// Generic layer (1..3): KK[(c*8+n), g*OM + o*8+m]
//   g<48 : Wc[o,c,(n-m)&7, r, (t-2m)&15]
//   g=48 : Wd[o,c,(m-n)&7]
template<int C, int O>
__global__ void expand_kernel(const float* __restrict__ Wc,
                              const float* __restrict__ Wd,
                              float* __restrict__ KK)
{
    constexpr int OM = O*8, NCOL = 49*OM, CN = C*8;
    int idx = blockIdx.x*blockDim.x + threadIdx.x;
    if (idx >= CN*NCOL) return;
    int k   = idx / NCOL;
    int col = idx - k*NCOL;
    int g   = col / OM;
    int om  = col - g*OM;
    int c = k>>3, n = k&7, o = om>>3, m = om&7;
    float v;
    if (g < 48) {
        int r = g>>4, t = g&15;
        v = Wc[(((o*C + c)*8 + ((n-m)&7))*3 + r)*16 + ((t - 2*m)&15)];
    } else {
        v = Wd[(o*C + c)*8 + ((m-n)&7)];
    }
    KK[k*NCOL + col] = v;
}

// Layer 0: lifts folded in. Input is raw feats (16 ch x 2 comp, K=32).
// KK0[(c*2+a), g*32 + o*8+m] = sum_n basis_a[n] * W...
__global__ void expand0_kernel(const float* __restrict__ Wc,
                               const float* __restrict__ Wd,
                               const float* __restrict__ lc,
                               const float* __restrict__ ld,
                               float* __restrict__ KK)
{
    int idx = blockIdx.x*blockDim.x + threadIdx.x;
    if (idx >= 32*1568) return;
    int k   = idx / 1568;
    int col = idx - k*1568;
    int c = k>>1, a = k&1;
    int g = col >> 5;
    int om = col & 31;
    int o = om>>3, m = om&7;
    float s = 0.f;
    if (g < 48) {
        int r = g>>4, t = g&15;
        float l0 = lc[0], l1 = lc[1];
        #pragma unroll
        for (int n = 0; n < 8; n++) {
            float sn, cs; sincosf((float)n*THETA0, &sn, &cs);
            float bas = a ? (l0*sn + l1*cs) : (l0*cs - l1*sn);
            s += bas * Wc[(((o*16 + c)*8 + ((n-m)&7))*3 + r)*16 + ((t - 2*m)&15)];
        }
    } else {
        float l0 = ld[0], l1 = ld[1];
        #pragma unroll
        for (int n = 0; n < 8; n++) {
            float sn, cs; sincosf((float)n*THETA0, &sn, &cs);
            float bas = a ? (l0*sn + l1*cs) : (l0*cs - l1*sn);
            s += bas * Wd[(o*16 + c)*8 + ((m-n)&7)];
        }
    }
    KK[k*1568 + col] = s;
}

// Layer 4: rho1 projection folded in. Output cols = g*6 + o*2 + a (294, stride 304).
__global__ void expand4_kernel(const float* __restrict__ Wc,
                               const float* __restrict__ Wd,
                               const float* __restrict__ pc,
                               const float* __restrict__ pd,
                               float* __restrict__ KK)
{
    int idx = blockIdx.x*blockDim.x + threadIdx.x;
    if (idx >= 64*294) return;
    int k   = idx / 294;
    int col = idx - k*294;
    int c = k>>3, n = k&7;
    int g  = col / 6;
    int oa = col - g*6;
    int o = oa>>1, a = oa&1;
    float s = 0.f;
    if (g < 48) {
        int r = g>>4, t = g&15;
        float c0 = pc[0], c1 = pc[1];
        #pragma unroll
        for (int m = 0; m < 8; m++) {
            float sn, cs; sincosf((float)m*THETA0, &sn, &cs);
            float bas = a ? (c0*sn + c1*cs) : (c0*cs - c1*sn);
            s += bas * Wc[(((o*8 + c)*8 + ((n-m)&7))*3 + r)*16 + ((t - 2*m)&15)];
        }
    } else {
        float d0 = pd[0], d1 = pd[1];
        #pragma unroll
        for (int m = 0; m < 8; m++) {
            float sn, cs; sincosf((float)m*THETA0, &sn, &cs);
            float bas = a ? (d0*sn + d1*cs) : (d0*cs - d1*sn);
            s += bas * Wd[(o*8 + c)*8 + ((m-n)&7)];
        }
    }
    KK[k*304 + col] = s;
}

// ---------------- GEMM: Y[1024 x NCOLP] = A[1024 x K] * KK[K x NCOLP] ----------
template<int K>
__global__ void __launch_bounds__(256)
gemm_kernel(const float* __restrict__ A, const float* __restrict__ B,
            float* __restrict__ C, int ncolp)
{
    __shared__ float As[16][64];   // [k][m]
    __shared__ float Bs[16][64];   // [k][n]
    int tid  = threadIdx.x;
    int row0 = blockIdx.y * 64;
    int col0 = blockIdx.x * 64;
    int ty = tid >> 4, tx = tid & 15;
    float acc[4][4] = {};

    for (int k0 = 0; k0 < K; k0 += 16) {
        {   // A tile: 64 rows x 16 k
            int r  = tid >> 2;
            int kq = (tid & 3) * 4;
            float4 av = *(const float4*)(A + (size_t)(row0 + r)*K + k0 + kq);
            As[kq+0][r] = av.x; As[kq+1][r] = av.y;
            As[kq+2][r] = av.z; As[kq+3][r] = av.w;
        }
        {   // B tile: 16 k x 64 n
            int kr = tid >> 4;
            int nq = (tid & 15) * 4;
            int col = col0 + nq;
            float4 bv = make_float4(0.f,0.f,0.f,0.f);
            if (col < ncolp)
                bv = *(const float4*)(B + (size_t)(k0 + kr)*ncolp + col);
            *(float4*)&Bs[kr][nq] = bv;
        }
        __syncthreads();
        #pragma unroll
        for (int kk = 0; kk < 16; kk++) {
            float4 av = *(const float4*)&As[kk][ty*4];
            float4 bv = *(const float4*)&Bs[kk][tx*4];
            float aa[4] = {av.x, av.y, av.z, av.w};
            float bb[4] = {bv.x, bv.y, bv.z, bv.w};
            #pragma unroll
            for (int ii = 0; ii < 4; ii++)
                #pragma unroll
                for (int jj = 0; jj < 4; jj++)
                    acc[ii][jj] += aa[ii] * bb[jj];
        }
        __syncthreads();
    }
    int colw = col0 + tx*4;
    if (colw < ncolp) {
        #pragma unroll
        for (int ii = 0; ii < 4; ii++) {
            float4 v = make_float4(acc[ii][0], acc[ii][1], acc[ii][2], acc[ii][3]);
            *(float4*)(C + (size_t)(row0 + ty*4 + ii)*ncolp + colw) = v;
        }
    }
}

// ---------------- neighbor gather ----------------
// MODE 0: out = conv + dense; MODE 1: concat(conv, dense) (layer 0);
// MODE 2: out = conv + dense + residual
template<int OM, int NI, int MODE>
__global__ void __launch_bounds__(OM*NI)
gather_kernel(const float* __restrict__ Y, int ncolp,
              const float* __restrict__ Res, float* __restrict__ Out)
{
    int tid  = threadIdx.x;
    int ig   = tid / OM;
    int lane = tid % OM;
    int bn   = blockIdx.x*NI + ig;
    int b    = bn >> 9;
    const float* Yb = Y + (size_t)(b*NP)*ncolp;
    int cnt = d_nbrCnt[bn];
    int pb  = bn*MAXN;
    float a0=0.f, a1=0.f, a2=0.f, a3=0.f;
    for (int e = 0; e < cnt; e++) {
        unsigned j  = d_nbrJ[pb+e];
        unsigned gp = d_nbrG[pb+e];
        float4   w  = d_nbrW[pb+e];
        const float* Yj = Yb + (size_t)j*ncolp + lane;
        a0 += w.x * __ldg(Yj + ( gp        & 255u)*OM);
        a1 += w.y * __ldg(Yj + ((gp >>  8) & 255u)*OM);
        a2 += w.z * __ldg(Yj + ((gp >> 16) & 255u)*OM);
        a3 += w.w * __ldg(Yj + ( gp >> 24        )*OM);
    }
    float conv  = (a0 + a1) + (a2 + a3);
    float dense = __ldg(Yb + (size_t)(bn & 511)*ncolp + 48*OM + lane);
    if (MODE == 1) {
        Out[bn*(2*OM) + lane]      = conv;
        Out[bn*(2*OM) + OM + lane] = dense;
    } else {
        float v = conv + dense;
        if (MODE == 2) v += Res[bn*OM + lane];
        Out[bn*OM + lane] = v;
    }
}

// Final layer gather: OM=6 (projected), epilogue writes p_corr/v_corr/m_matrix
__global__ void __launch_bounds__(128)
gather4_kernel(const float* __restrict__ Y, const float* __restrict__ p0,
               float* __restrict__ out)
{
    int tid  = threadIdx.x;
    int ig   = tid >> 3;
    int lane = tid & 7;
    int bn   = blockIdx.x*16 + ig;
    if (lane >= 6) return;
    int b = bn >> 9;
    const float* Yb = Y + (size_t)(b*NP)*304;
    int cnt = d_nbrCnt[bn];
    int pb  = bn*MAXN;
    float a0=0.f, a1=0.f, a2=0.f, a3=0.f;
    for (int e = 0; e < cnt; e++) {
        unsigned j  = d_nbrJ[pb+e];
        unsigned gp = d_nbrG[pb+e];
        float4   w  = d_nbrW[pb+e];
        const float* Yj = Yb + (size_t)j*304 + lane;
        a0 += w.x * __ldg(Yj + ( gp        & 255u)*6);
        a1 += w.y * __ldg(Yj + ((gp >>  8) & 255u)*6);
        a2 += w.z * __ldg(Yj + ((gp >> 16) & 255u)*6);
        a3 += w.w * __ldg(Yj + ( gp >> 24        )*6);
    }
    float s = (a0 + a1) + (a2 + a3)
            + __ldg(Yb + (size_t)(bn & 511)*304 + 288 + lane);
    float pcv = s * 0.0078125f;    // CORR = 1/128
    int o = lane >> 1, a = lane & 1;
    if (o == 0) {
        float pc = d_p1[bn*2 + a] + pcv;
        out[bn*2 + a]          = pc;                      // p_corr
        out[2*BN + bn*2 + a]   = pc - p0[bn*2 + a];       // v_corr (DT=1)
    } else {
        out[4*BN + (bn*2 + (o-1))*2 + a] = pcv;           // m_matrix
    }
}

// ---------------- mag_act ----------------
template<int C>
__global__ void magact_kernel(const float* __restrict__ Y, float* __restrict__ Xo)
{
    int idx = blockIdx.x*blockDim.x + threadIdx.x;
    if (idx >= BN*C) return;
    const float4* y4 = (const float4*)(Y + idx*8);
    float4 a = y4[0], b = y4[1];
    float mg = 1e-6f + a.x*a.x + a.y*a.y + a.z*a.z + a.w*a.w
                     + b.x*b.x + b.y*b.y + b.z*b.z + b.w*b.w;
    float s = fmaxf(mg - 0.2f, 0.f) / mg;
    float4* o4 = (float4*)(Xo + idx*8);
    o4[0] = make_float4(a.x*s, a.y*s, a.z*s, a.w*s);
    o4[1] = make_float4(b.x*s, b.y*s, b.z*s, b.w*s);
}

// ---------------- launch ----------------
extern "C" void kernel_launch(void* const* d_in, const int* in_sizes, int n_in,
                              void* d_out, int out_size)
{
    (void)in_sizes; (void)n_in; (void)out_size;
    const float* p0_enc = (const float*)d_in[0];
    const float* v0_enc = (const float*)d_in[1];
    const float* p0     = (const float*)d_in[2];
    const float* v0     = (const float*)d_in[3];
    const float* a      = (const float*)d_in[4];
    const float* fm     = (const float*)d_in[5];
    const float* lift_c0= (const float*)d_in[6];
    const float* Wc0    = (const float*)d_in[7];
    const float* lift_d0= (const float*)d_in[8];
    const float* Wd0    = (const float*)d_in[9];
    const float* Wc1    = (const float*)d_in[10];
    const float* Wd1    = (const float*)d_in[11];
    const float* Wc2    = (const float*)d_in[12];
    const float* Wd2    = (const float*)d_in[13];
    const float* Wc3    = (const float*)d_in[14];
    const float* Wd3    = (const float*)d_in[15];
    const float* Wc4    = (const float*)d_in[16];
    const float* pc4    = (const float*)d_in[17];
    const float* Wd4    = (const float*)d_in[18];
    const float* pd4    = (const float*)d_in[19];
    float* out = (float*)d_out;

    float *pF0, *pY, *pK0, *pK1, *pK2, *pK3, *pK4;
    float *pR0, *pA0, *pR1, *pA1, *pR2, *pA2, *pR3, *pA3;
    cudaGetSymbolAddress((void**)&pF0, d_F0);
    cudaGetSymbolAddress((void**)&pY,  d_Y);
    cudaGetSymbolAddress((void**)&pK0, d_KK0);
    cudaGetSymbolAddress((void**)&pK1, d_KK1);
    cudaGetSymbolAddress((void**)&pK2, d_KK2);
    cudaGetSymbolAddress((void**)&pK3, d_KK3);
    cudaGetSymbolAddress((void**)&pK4, d_KK4);
    cudaGetSymbolAddress((void**)&pR0, d_R0);
    cudaGetSymbolAddress((void**)&pA0, d_A0);
    cudaGetSymbolAddress((void**)&pR1, d_R1);
    cudaGetSymbolAddress((void**)&pA1, d_A1);
    cudaGetSymbolAddress((void**)&pR2, d_R2);
    cudaGetSymbolAddress((void**)&pA2, d_A2);
    cudaGetSymbolAddress((void**)&pR3, d_R3);
    cudaGetSymbolAddress((void**)&pA3, d_A3);

    prep_kernel<<<(BN*16 + 127)/128, 128>>>(p0_enc, v0_enc, p0, v0, a);
    pair_kernel<<<BN, 256>>>(fm);

    // weight expansions (all independent of particle data)
    expand0_kernel<<<(32*1568 + 255)/256, 256>>>(Wc0, Wd0, lift_c0, lift_d0, pK0);
    expand_kernel<8,8>  <<<(64*3136 + 255)/256, 256>>>(Wc1, Wd1, pK1);
    expand_kernel<8,16> <<<(64*6272 + 255)/256, 256>>>(Wc2, Wd2, pK2);
    expand_kernel<16,8> <<<(128*3136 + 255)/256, 256>>>(Wc3, Wd3, pK3);
    expand4_kernel<<<(64*294 + 255)/256, 256>>>(Wc4, Wd4, pc4, pd4, pK4);

    // L0: K=32 raw feats -> Y[.,1568]; gather concat(conv32, dense32) -> R0
    gemm_kernel<32><<<dim3((1568+63)/64, 16), 256>>>(pF0, pK0, pY, 1568);
    gather_kernel<32,4,1><<<BN/4, 128>>>(pY, 1568, nullptr, pR0);
    magact_kernel<8><<<(BN*8 + 127)/128, 128>>>(pR0, pA0);

    // L1: C=8 -> O=8, residual += R0
    gemm_kernel<64><<<dim3((3136+63)/64, 16), 256>>>(pA0, pK1, pY, 3136);
    gather_kernel<64,2,2><<<BN/2, 128>>>(pY, 3136, pR0, pR1);
    magact_kernel<8><<<(BN*8 + 127)/128, 128>>>(pR1, pA1);

    // L2: C=8 -> O=16
    gemm_kernel<64><<<dim3((6272+63)/64, 16), 256>>>(pA1, pK2, pY, 6272);
    gather_kernel<128,1,0><<<BN, 128>>>(pY, 6272, nullptr, pR2);
    magact_kernel<16><<<(BN*16 + 127)/128, 128>>>(pR2, pA2);

    // L3: C=16 -> O=8
    gemm_kernel<128><<<dim3((3136+63)/64, 16), 256>>>(pA2, pK3, pY, 3136);
    gather_kernel<64,2,0><<<BN/2, 128>>>(pY, 3136, nullptr, pR3);
    magact_kernel<8><<<(BN*8 + 127)/128, 128>>>(pR3, pA3);

    // L4: C=8 -> projected 6 outputs, fused epilogue
    gemm_kernel<64><<<dim3((304+63)/64, 16), 256>>>(pA3, pK4, pY, 304);
    gather4_kernel<<<BN/16, 128>>>(pY, p0, out);
}